// round 7
// baseline (speedup 1.0000x reference)
#include <cuda_runtime.h>
#include <cstdint>

// UltraTinyGRU fused, smem-staged, MUFU.TANH, f32x2 dots, 2-way row interleave.
// B=4096, T=512, F=16, H=4.
// Block = 64 threads = 16 quads; each quad runs TWO independent rows
// (row2 and row2+16) with their chains interleaved -> fills the warp's idle
// issue slots during tanh/shfl latency. 128 blocks, 1/SM.

#define GT 512
#define ROWS 32           // rows per block (16 quads x 2)
#define THREADS 64
#define SSTEPS 8
#define NSTAGE (GT / SSTEPS)

__device__ __forceinline__ void cp_async16(void* smem_dst, const void* gmem_src) {
    unsigned int s = (unsigned int)__cvta_generic_to_shared(smem_dst);
    asm volatile("cp.async.cg.shared.global [%0], [%1], 16;\n"
                 :: "r"(s), "l"(gmem_src) : "memory");
}
__device__ __forceinline__ void cp_async_commit() {
    asm volatile("cp.async.commit_group;\n" ::: "memory");
}

__device__ __forceinline__ float tanh_fast(float x) {
    float y;
    asm("tanh.approx.f32 %0, %1;" : "=f"(y) : "f"(x));
    return y;
}

// ---- packed fp32x2 helpers ----
__device__ __forceinline__ double pack2(float lo, float hi) {
    double d;
    asm("mov.b64 %0, {%1, %2};" : "=d"(d) : "f"(lo), "f"(hi));
    return d;
}
__device__ __forceinline__ double fma2(double a, double b, double c) {
    double d;
    asm("fma.rn.f32x2 %0, %1, %2, %3;" : "=d"(d) : "d"(a), "d"(b), "d"(c));
    return d;
}
__device__ __forceinline__ double mul2(double a, double b) {
    double d;
    asm("mul.rn.f32x2 %0, %1, %2;" : "=d"(d) : "d"(a), "d"(b));
    return d;
}
__device__ __forceinline__ double add2(double a, double b) {
    double d;
    asm("add.rn.f32x2 %0, %1, %2;" : "=d"(d) : "d"(a), "d"(b));
    return d;
}
__device__ __forceinline__ float2 unpack2(double d) {
    float2 r;
    asm("mov.b64 {%0, %1}, %2;" : "=f"(r.x), "=f"(r.y) : "d"(d));
    return r;
}

__device__ __forceinline__ void pack_row(float4 v, float scale, double* dst) {
    dst[0] = pack2(v.x * scale, v.y * scale);
    dst[1] = pack2(v.z * scale, v.w * scale);
}

// packed 16-dot: acc-seeded tree
__device__ __forceinline__ float pdot16(const double2 q0, const double2 q1,
                                        const double2 q2, const double2 q3,
                                        const double* w, double bias) {
    double a = fma2(q0.x, w[0], bias);
    a = fma2(q0.y, w[1], a);
    a = fma2(q1.x, w[2], a);
    a = fma2(q1.y, w[3], a);
    double b = mul2(q2.x, w[4]);
    b = fma2(q2.y, w[5], b);
    b = fma2(q3.x, w[6], b);
    b = fma2(q3.y, w[7], b);
    const float2 u = unpack2(add2(a, b));
    return u.x + u.y;
}

struct GruState {
    float h0, h1, h2, h3, hhalf;
};

__global__ __launch_bounds__(THREADS, 1)
void gru_fused(const float* __restrict__ x,
               const float* __restrict__ w_ih,
               const float* __restrict__ w_hh,
               const float* __restrict__ b_ih,
               const float* __restrict__ b_hh,
               const float* __restrict__ fc_w,
               const float* __restrict__ fc_b,
               float* __restrict__ out) {
    // [2 stages][32 rows][33 float4] = 33.8KB; 528B row stride (bank-spread)
    __shared__ float4 sx[2][ROWS][33];

    const int tid  = threadIdx.x;
    const int b0   = blockIdx.x * ROWS;
    const int row2 = tid >> 2;        // 0..15
    const int j    = tid & 3;

    // ---- pack input-side weights; r/z rows pre-halved ----
    const float4* W = (const float4*)w_ih;
    double wrP[8], wzP[8], wnP[8];
#pragma unroll
    for (int q = 0; q < 4; q++) {
        pack_row(__ldg(&W[(j)     * 4 + q]), 0.5f, &wrP[q * 2]);
        pack_row(__ldg(&W[(4 + j) * 4 + q]), 0.5f, &wzP[q * 2]);
        pack_row(__ldg(&W[(8 + j) * 4 + q]), 1.0f, &wnP[q * 2]);
    }

    const float4* Wh = (const float4*)w_hh;
    float4 whr = __ldg(&Wh[j]);
    float4 whz = __ldg(&Wh[4 + j]);
    float4 whn = __ldg(&Wh[8 + j]);
    whr.x *= 0.5f; whr.y *= 0.5f; whr.z *= 0.5f; whr.w *= 0.5f;
    whz.x *= 0.5f; whz.y *= 0.5f; whz.z *= 0.5f; whz.w *= 0.5f;
    whn.x *= 0.5f; whn.y *= 0.5f; whn.z *= 0.5f; whn.w *= 0.5f;

    const float brh  = 0.5f * (__ldg(&b_ih[j])     + __ldg(&b_hh[j]));
    const float bzh  = 0.5f * (__ldg(&b_ih[4 + j]) + __ldg(&b_hh[4 + j]));
    const float bin  = __ldg(&b_ih[8 + j]);
    const float bhnh = 0.5f * __ldg(&b_hh[8 + j]);

    const double biasR = pack2(brh, 0.0f);
    const double biasZ = pack2(bzh, 0.0f);
    const double biasN = pack2(bin, 0.0f);

    // ---- stage copy: 64 threads move 32 rows x 512B = 1024 x 16B ----
    const float4* xbase = (const float4*)x;
    auto issue_stage = [&](int s, int buf) {
#pragma unroll
        for (int it = 0; it < 16; it++) {
            const int c     = tid + it * THREADS;
            const int crow  = c >> 5;
            const int chunk = c & 31;
            const float4* src = xbase + ((size_t)(b0 + crow) * GT + s * SSTEPS) * 4 + chunk;
            cp_async16(&sx[buf][crow][chunk], src);
        }
        cp_async_commit();
    };

    issue_stage(0, 0);
    issue_stage(1, 1);

    GruState sA = {0.f, 0.f, 0.f, 0.f, 0.f};
    GruState sB = {0.f, 0.f, 0.f, 0.f, 0.f};

    // one GRU step for one row; chain: hdots -> tanh -> fma -> tanh -> update -> shfl
    auto step = [&](GruState& st, const double2* rx2, int u) {
        const double2 q0 = rx2[u * 4 + 0];
        const double2 q1 = rx2[u * 4 + 1];
        const double2 q2 = rx2[u * 4 + 2];
        const double2 q3 = rx2[u * 4 + 3];

        const float grh = pdot16(q0, q1, q2, q3, wrP, biasR);
        const float gzh = pdot16(q0, q1, q2, q3, wzP, biasZ);
        const float gnf = pdot16(q0, q1, q2, q3, wnP, biasN);

        float ar = fmaf(st.h0, whr.x, grh); ar = fmaf(st.h1, whr.y, ar);
        float cr = st.h2 * whr.z;           cr = fmaf(st.h3, whr.w, cr);
        const float arg_r = ar + cr;

        float az = fmaf(st.h0, whz.x, gzh); az = fmaf(st.h1, whz.y, az);
        float cz = st.h2 * whz.z;           cz = fmaf(st.h3, whz.w, cz);
        const float arg_z = az + cz;

        float an = fmaf(st.h0, whn.x, bhnh); an = fmaf(st.h1, whn.y, an);
        float cn = st.h2 * whn.z;            cn = fmaf(st.h3, whn.w, cn);
        const float ghn_h = an + cn;         // 0.5*(h.w_hh_n + b_hh_n)

        const float tr = tanh_fast(arg_r);
        const float tz = tanh_fast(arg_z);

        const float gnp  = gnf + ghn_h;
        const float narg = fmaf(tr, ghn_h, gnp);
        const float n    = tanh_fast(narg);

        const float dd = fmaf(n, -0.5f, st.hhalf);  // 0.5*(h_own - n)
        const float nt = n + dd;
        const float hn = fmaf(tz, dd, nt);

        st.hhalf = 0.5f * hn;
        st.h0 = __shfl_sync(0xffffffffu, hn, 0, 4);
        st.h1 = __shfl_sync(0xffffffffu, hn, 1, 4);
        st.h2 = __shfl_sync(0xffffffffu, hn, 2, 4);
        st.h3 = __shfl_sync(0xffffffffu, hn, 3, 4);
    };

    for (int s = 0; s < NSTAGE; s++) {
        if (s == NSTAGE - 1) {
            asm volatile("cp.async.wait_group 0;\n" ::: "memory");
        } else {
            asm volatile("cp.async.wait_group 1;\n" ::: "memory");
        }
        __syncthreads();

        const double2* rxA = (const double2*)&sx[s & 1][row2][0];
        const double2* rxB = (const double2*)&sx[s & 1][row2 + 16][0];
#pragma unroll
        for (int u = 0; u < SSTEPS; u++) {
            step(sA, rxA, u);   // the two chains are independent;
            step(sB, rxB, u);   // ptxas interleaves them after inlining
        }
        __syncthreads();

        if (s < NSTAGE - 2) {
            issue_stage(s + 2, s & 1);
        }
    }

    if (j == 0) {
        const float fw0 = __ldg(&fc_w[0]), fw1 = __ldg(&fc_w[1]);
        const float fw2 = __ldg(&fc_w[2]), fw3 = __ldg(&fc_w[3]);
        const float fb  = __ldg(&fc_b[0]);
        out[b0 + row2]      = (sA.h0 * fw0 + sA.h1 * fw1) + (sA.h2 * fw2 + sA.h3 * fw3) + fb;
        out[b0 + row2 + 16] = (sB.h0 * fw0 + sB.h1 * fw1) + (sB.h2 * fw2 + sB.h3 * fw3) + fb;
    }
}

extern "C" void kernel_launch(void* const* d_in, const int* in_sizes, int n_in,
                              void* d_out, int out_size) {
    const float* x    = (const float*)d_in[0];
    const float* w_ih = (const float*)d_in[1];
    const float* w_hh = (const float*)d_in[2];
    const float* b_ih = (const float*)d_in[3];
    const float* b_hh = (const float*)d_in[4];
    const float* fc_w = (const float*)d_in[5];
    const float* fc_b = (const float*)d_in[6];
    float* out = (float*)d_out;

    const int B = out_size;          // 4096
    const int blocks = B / ROWS;     // 128

    gru_fused<<<blocks, THREADS>>>(x, w_ih, w_hh, b_ih, b_hh, fc_w, fc_b, out);
}

// round 9
// speedup vs baseline: 1.4865x; 1.4865x over previous
#include <cuda_runtime.h>
#include <cstdint>

// UltraTinyGRU fused, smem-staged, MUFU.TANH, f32x2 dots,
// software-pipelined: step u+1's input dots are computed inside step u's
// tanh stall windows (in-order issue means fill work must be placed there
// textually). Layout = R6: 128 blocks x 128 threads, 1 row per quad,
// 512 warps ~ one per SMSP.

#define GT 512
#define ROWS 32
#define THREADS 128
#define SSTEPS 8
#define NSTAGE (GT / SSTEPS)

__device__ __forceinline__ void cp_async16(void* smem_dst, const void* gmem_src) {
    unsigned int s = (unsigned int)__cvta_generic_to_shared(smem_dst);
    asm volatile("cp.async.cg.shared.global [%0], [%1], 16;\n"
                 :: "r"(s), "l"(gmem_src) : "memory");
}
__device__ __forceinline__ void cp_async_commit() {
    asm volatile("cp.async.commit_group;\n" ::: "memory");
}

__device__ __forceinline__ float tanh_fast(float x) {
    float y;
    asm("tanh.approx.f32 %0, %1;" : "=f"(y) : "f"(x));
    return y;
}

// ---- packed fp32x2 helpers ----
__device__ __forceinline__ double pack2(float lo, float hi) {
    double d;
    asm("mov.b64 %0, {%1, %2};" : "=d"(d) : "f"(lo), "f"(hi));
    return d;
}
__device__ __forceinline__ double fma2(double a, double b, double c) {
    double d;
    asm("fma.rn.f32x2 %0, %1, %2, %3;" : "=d"(d) : "d"(a), "d"(b), "d"(c));
    return d;
}
__device__ __forceinline__ double mul2(double a, double b) {
    double d;
    asm("mul.rn.f32x2 %0, %1, %2;" : "=d"(d) : "d"(a), "d"(b));
    return d;
}
__device__ __forceinline__ double add2(double a, double b) {
    double d;
    asm("add.rn.f32x2 %0, %1, %2;" : "=d"(d) : "d"(a), "d"(b));
    return d;
}
__device__ __forceinline__ float2 unpack2(double d) {
    float2 r;
    asm("mov.b64 {%0, %1}, %2;" : "=f"(r.x), "=f"(r.y) : "d"(d));
    return r;
}

__device__ __forceinline__ void pack_row(float4 v, float scale, double* dst) {
    dst[0] = pack2(v.x * scale, v.y * scale);
    dst[1] = pack2(v.z * scale, v.w * scale);
}

__device__ __forceinline__ float pdot16(const double2 q0, const double2 q1,
                                        const double2 q2, const double2 q3,
                                        const double* w, double bias) {
    double a = fma2(q0.x, w[0], bias);
    a = fma2(q0.y, w[1], a);
    a = fma2(q1.x, w[2], a);
    a = fma2(q1.y, w[3], a);
    double b = mul2(q2.x, w[4]);
    b = fma2(q2.y, w[5], b);
    b = fma2(q3.x, w[6], b);
    b = fma2(q3.y, w[7], b);
    const float2 u = unpack2(add2(a, b));
    return u.x + u.y;
}

__global__ __launch_bounds__(THREADS, 1)
void gru_fused(const float* __restrict__ x,
               const float* __restrict__ w_ih,
               const float* __restrict__ w_hh,
               const float* __restrict__ b_ih,
               const float* __restrict__ b_hh,
               const float* __restrict__ fc_w,
               const float* __restrict__ fc_b,
               float* __restrict__ out) {
    __shared__ float4 sx[2][ROWS][33];   // 528B row stride

    const int tid = threadIdx.x;
    const int b0  = blockIdx.x * ROWS;
    const int row = tid >> 2;
    const int j   = tid & 3;
    const int b   = b0 + row;

    // ---- packed input weights; r/z pre-halved (sigmoid->tanh fold) ----
    const float4* W = (const float4*)w_ih;
    double wrP[8], wzP[8], wnP[8];
#pragma unroll
    for (int q = 0; q < 4; q++) {
        pack_row(__ldg(&W[(j)     * 4 + q]), 0.5f, &wrP[q * 2]);
        pack_row(__ldg(&W[(4 + j) * 4 + q]), 0.5f, &wzP[q * 2]);
        pack_row(__ldg(&W[(8 + j) * 4 + q]), 1.0f, &wnP[q * 2]);
    }

    const float4* Wh = (const float4*)w_hh;
    float4 whr = __ldg(&Wh[j]);
    float4 whz = __ldg(&Wh[4 + j]);
    float4 whn = __ldg(&Wh[8 + j]);
    whr.x *= 0.5f; whr.y *= 0.5f; whr.z *= 0.5f; whr.w *= 0.5f;
    whz.x *= 0.5f; whz.y *= 0.5f; whz.z *= 0.5f; whz.w *= 0.5f;
    whn.x *= 0.5f; whn.y *= 0.5f; whn.z *= 0.5f; whn.w *= 0.5f;

    const float brh  = 0.5f * (__ldg(&b_ih[j])     + __ldg(&b_hh[j]));
    const float bzh  = 0.5f * (__ldg(&b_ih[4 + j]) + __ldg(&b_hh[4 + j]));
    const float bin  = __ldg(&b_ih[8 + j]);
    const float bhnh = 0.5f * __ldg(&b_hh[8 + j]);

    const double biasR = pack2(brh, 0.0f);
    const double biasZ = pack2(bzh, 0.0f);
    const double biasN = pack2(bin, 0.0f);

    // ---- stage copy: 128 threads move 32 rows x 512B ----
    const float4* xbase = (const float4*)x;
    auto issue_stage = [&](int s, int buf) {
#pragma unroll
        for (int it = 0; it < 8; it++) {
            const int c     = tid + it * THREADS;
            const int crow  = c >> 5;
            const int chunk = c & 31;
            const float4* src = xbase + ((size_t)(b0 + crow) * GT + s * SSTEPS) * 4 + chunk;
            cp_async16(&sx[buf][crow][chunk], src);
        }
        cp_async_commit();
    };

    issue_stage(0, 0);
    issue_stage(1, 1);

    float h0 = 0.f, h1 = 0.f, h2 = 0.f, h3 = 0.f;
    float hhalf = 0.f;

    for (int s = 0; s < NSTAGE; s++) {
        if (s == NSTAGE - 1) {
            asm volatile("cp.async.wait_group 0;\n" ::: "memory");
        } else {
            asm volatile("cp.async.wait_group 1;\n" ::: "memory");
        }
        __syncthreads();

        const double2* rx2 = (const double2*)&sx[s & 1][row][0];

        // prologue: dots for step 0 of this stage
        double2 q0 = rx2[0], q1 = rx2[1], q2 = rx2[2], q3 = rx2[3];
        float grC = pdot16(q0, q1, q2, q3, wrP, biasR);
        float gzC = pdot16(q0, q1, q2, q3, wzP, biasZ);
        float gnC = pdot16(q0, q1, q2, q3, wnP, biasN);

#pragma unroll
        for (int u = 0; u < SSTEPS; u++) {
            // ---- chain head: hidden-side dots ----
            float ar = fmaf(h0, whr.x, grC); ar = fmaf(h1, whr.y, ar);
            float cr = h2 * whr.z;           cr = fmaf(h3, whr.w, cr);
            const float arg_r = ar + cr;

            float az = fmaf(h0, whz.x, gzC); az = fmaf(h1, whz.y, az);
            float cz = h2 * whz.z;           cz = fmaf(h3, whz.w, cz);
            const float arg_z = az + cz;

            float an = fmaf(h0, whn.x, bhnh); an = fmaf(h1, whn.y, an);
            float cn = h2 * whn.z;            cn = fmaf(h3, whn.w, cn);
            const float ghn_h = an + cn;      // 0.5*(h.w_hh_n + b_hh_n)

            const float tr = tanh_fast(arg_r);
            const float tz = tanh_fast(arg_z);

            // ---- fill window: step u+1's loads + dots issue while the
            //      tanhs are in flight (in-order issue -> must sit here) ----
            float grN = 0.f, gzN = 0.f, gnN = 0.f;
            if (u < SSTEPS - 1) {
                const double2 p0 = rx2[(u + 1) * 4 + 0];
                const double2 p1 = rx2[(u + 1) * 4 + 1];
                const double2 p2 = rx2[(u + 1) * 4 + 2];
                const double2 p3 = rx2[(u + 1) * 4 + 3];
                grN = pdot16(p0, p1, p2, p3, wrP, biasR);
                gzN = pdot16(p0, p1, p2, p3, wzP, biasZ);
                gnN = pdot16(p0, p1, p2, p3, wnP, biasN);
            }

            // ---- chain tail ----
            const float gnp  = gnC + ghn_h;
            const float narg = fmaf(tr, ghn_h, gnp);
            const float n    = tanh_fast(narg);

            const float dd = fmaf(n, -0.5f, hhalf);   // 0.5*(h_own - n)
            const float nt = n + dd;
            const float hn = fmaf(tz, dd, nt);

            hhalf = 0.5f * hn;
            h0 = __shfl_sync(0xffffffffu, hn, 0, 4);
            h1 = __shfl_sync(0xffffffffu, hn, 1, 4);
            h2 = __shfl_sync(0xffffffffu, hn, 2, 4);
            h3 = __shfl_sync(0xffffffffu, hn, 3, 4);

            grC = grN; gzC = gzN; gnC = gnN;
        }
        __syncthreads();

        if (s < NSTAGE - 2) {
            issue_stage(s + 2, s & 1);
        }
    }

    if (j == 0) {
        const float fw0 = __ldg(&fc_w[0]), fw1 = __ldg(&fc_w[1]);
        const float fw2 = __ldg(&fc_w[2]), fw3 = __ldg(&fc_w[3]);
        out[b] = (h0 * fw0 + h1 * fw1) + (h2 * fw2 + h3 * fw3) + __ldg(&fc_b[0]);
    }
}

extern "C" void kernel_launch(void* const* d_in, const int* in_sizes, int n_in,
                              void* d_out, int out_size) {
    const float* x    = (const float*)d_in[0];
    const float* w_ih = (const float*)d_in[1];
    const float* w_hh = (const float*)d_in[2];
    const float* b_ih = (const float*)d_in[3];
    const float* b_hh = (const float*)d_in[4];
    const float* fc_w = (const float*)d_in[5];
    const float* fc_b = (const float*)d_in[6];
    float* out = (float*)d_out;

    const int B = out_size;          // 4096
    const int blocks = B / ROWS;     // 128

    gru_fused<<<blocks, THREADS>>>(x, w_ih, w_hh, b_ih, b_hh, fc_w, fc_b, out);
}